// round 16
// baseline (speedup 1.0000x reference)
#include <cuda_runtime.h>
#include <cuda_bf16.h>
#include <cstdint>

#define D_MODEL 1024
#define NH 16
#define DH 64
#define SEQ 2048
#define BATCH 2
#define BH (BATCH * NH)        // 32
#define M_ROWS (BATCH * SEQ)   // 4096
#define N_QKV (3 * NH * DH)    // 3072

// Scratch
__device__ __align__(16) float g_QKV[(size_t)M_ROWS * N_QKV];
__device__ __align__(16) __nv_bfloat16 g_Qhi[(size_t)BH * SEQ * DH];
__device__ __align__(16) __nv_bfloat16 g_Qlo[(size_t)BH * SEQ * DH];
__device__ __align__(16) __nv_bfloat16 g_Khi[(size_t)BH * SEQ * DH];
__device__ __align__(16) __nv_bfloat16 g_Klo[(size_t)BH * SEQ * DH];
__device__ __align__(16) __nv_bfloat16 g_Vthi[(size_t)BH * DH * SEQ];
__device__ __align__(16) __nv_bfloat16 g_Vtlo[(size_t)BH * DH * SEQ];
__device__ float g_A[(size_t)M_ROWS * D_MODEL];

// ---------------------------------------------------------------------------
__device__ __forceinline__ float exp2_fast(float x)
{
    x = fmaxf(x, -80.0f);
    float z = x + 12582912.0f;
    int   n = __float_as_int(z) - 0x4B400000;
    float f = x - (z - 12582912.0f);
    float p = 1.3369700e-3f;
    p = fmaf(p, f, 9.6179365e-3f);
    p = fmaf(p, f, 5.5503264e-2f);
    p = fmaf(p, f, 2.4022736e-1f);
    p = fmaf(p, f, 6.9314693e-1f);
    p = fmaf(p, f, 1.0f);
    return __int_as_float(__float_as_int(p) + (n << 23));
}

__device__ __forceinline__ uint32_t smem_u32(const void* p) {
    uint32_t a;
    asm("{ .reg .u64 t; cvta.to.shared.u64 t, %1; cvt.u32.u64 %0, t; }"
        : "=r"(a) : "l"(p));
    return a;
}

// returns {second arg in bits 31:16, first arg in bits 15:0}
__device__ __forceinline__ uint32_t pack_bf16(float lo_elem, float hi_elem) {
    uint32_t r;
    asm("cvt.rn.bf16x2.f32 %0, %1, %2;" : "=r"(r) : "f"(hi_elem), "f"(lo_elem));
    return r;
}

__device__ __forceinline__ float bf16_rnf(float x) {
    return __bfloat162float(__float2bfloat16(x));
}

__device__ __forceinline__ void mma_bf16(float* c, const uint32_t* a,
                                         uint32_t b0, uint32_t b1) {
    asm volatile(
        "mma.sync.aligned.m16n8k16.row.col.f32.bf16.bf16.f32 "
        "{%0,%1,%2,%3}, {%4,%5,%6,%7}, {%8,%9}, {%0,%1,%2,%3};"
        : "+f"(c[0]), "+f"(c[1]), "+f"(c[2]), "+f"(c[3])
        : "r"(a[0]), "r"(a[1]), "r"(a[2]), "r"(a[3]), "r"(b0), "r"(b1));
}

#define MMA4(C0,C1,C2,C3,A0,A1,A2,A3,B0,B1) \
    asm volatile("mma.sync.aligned.m16n8k16.row.col.f32.bf16.bf16.f32 " \
        "{%0,%1,%2,%3}, {%4,%5,%6,%7}, {%8,%9}, {%0,%1,%2,%3};" \
        : "+f"(C0), "+f"(C1), "+f"(C2), "+f"(C3) \
        : "r"(A0), "r"(A1), "r"(A2), "r"(A3), "r"(B0), "r"(B1))

#define CP_ASYNC16(dst, src) \
    asm volatile("cp.async.cg.shared.global [%0], [%1], 16;" \
                 :: "r"(dst), "l"(src))
#define CP_COMMIT() asm volatile("cp.async.commit_group;" ::: "memory")
#define CP_WAIT0()  asm volatile("cp.async.wait_group 0;" ::: "memory")
#define CP_WAIT1()  asm volatile("cp.async.wait_group 1;" ::: "memory")

// ---------------------------------------------------------------------------
// Geometry
// ---------------------------------------------------------------------------
#define TSTRIDE 72
#define TBYTES  (64 * TSTRIDE * 2)      // 9216  (64-row tensor)
#define STAGEB  (4 * TBYTES)            // 36864
#define SMEM_ATTN (2 * STAGEB)          // flash double-buffered: 73728
#define SMEM_GEMM STAGEB                // gemm single-buffered: 36864

// ---------------------------------------------------------------------------
// Fused-split mma GEMM, tile 64m x 64n, 128 threads, K-chunk 64, with
// REGISTER PREFETCH software pipeline: chunk t+1's LDGs are in flight
// while chunk t's mma runs.
//   C[M_ROWS, N] = X[M_ROWS,1024] @ W[1024, N]   (all fp32 in/out)
// grid: (N/64, M_ROWS/64), block 128.
// ---------------------------------------------------------------------------
#define LOAD_A(KG) do {                                         \
    int r0_ = abase + (KG) * 16;                                \
    int r8_ = r0_ + 8 * TSTRIDE;                                \
    ah##KG##0 = *(const uint32_t*)(sAh + r0_);                  \
    ah##KG##1 = *(const uint32_t*)(sAh + r8_);                  \
    ah##KG##2 = *(const uint32_t*)(sAh + r0_ + 8);              \
    ah##KG##3 = *(const uint32_t*)(sAh + r8_ + 8);              \
    al##KG##0 = *(const uint32_t*)(sAl + r0_);                  \
    al##KG##1 = *(const uint32_t*)(sAl + r8_);                  \
    al##KG##2 = *(const uint32_t*)(sAl + r0_ + 8);              \
    al##KG##3 = *(const uint32_t*)(sAl + r8_ + 8);              \
} while (0)

#define MMA_KG(NF, KG, BOFF) do {                               \
    uint32_t b0h_ = *(const uint32_t*)(sBh + (BOFF) + (KG)*16);     \
    uint32_t b1h_ = *(const uint32_t*)(sBh + (BOFF) + (KG)*16 + 8); \
    uint32_t b0l_ = *(const uint32_t*)(sBl + (BOFF) + (KG)*16);     \
    uint32_t b1l_ = *(const uint32_t*)(sBl + (BOFF) + (KG)*16 + 8); \
    MMA4(c##NF##0, c##NF##1, c##NF##2, c##NF##3,                \
         ah##KG##0, ah##KG##1, ah##KG##2, ah##KG##3, b0h_, b1h_); \
    MMA4(c##NF##0, c##NF##1, c##NF##2, c##NF##3,                \
         ah##KG##0, ah##KG##1, ah##KG##2, ah##KG##3, b0l_, b1l_); \
    MMA4(c##NF##0, c##NF##1, c##NF##2, c##NF##3,                \
         al##KG##0, al##KG##1, al##KG##2, al##KG##3, b0h_, b1h_); \
} while (0)

#define MMA_NF(NF) do {                                         \
    int boff_ = ((NF) * 8 + g) * TSTRIDE + lt2;                 \
    MMA_KG(NF, 0, boff_);                                       \
    MMA_KG(NF, 1, boff_);                                       \
    MMA_KG(NF, 2, boff_);                                       \
    MMA_KG(NF, 3, boff_);                                       \
} while (0)

#define STORE_NF(NF) do {                                       \
    int n_ = n0 + (NF) * 8 + lt2;                               \
    float2 u_; u_.x = c##NF##0; u_.y = c##NF##1;                \
    float2 w_; w_.x = c##NF##2; w_.y = c##NF##3;                \
    *(float2*)(C + (size_t)m_g  * N + n_) = u_;                 \
    *(float2*)(C + (size_t)m_g8 * N + n_) = w_;                 \
} while (0)

template <int N>
__global__ __launch_bounds__(128) void gemm_fused(
    const float* __restrict__ X, const float* __restrict__ W,
    float* __restrict__ C)
{
    extern __shared__ char sm[];

    const int tid  = threadIdx.x;
    const int warp = tid >> 5;          // 0..3
    const int lane = tid & 31;
    const int g    = lane >> 2;
    const int lt2  = (lane & 3) * 2;
    const int n0   = blockIdx.x * 64;
    const int m0   = blockIdx.y * 64;

    const __nv_bfloat16* sAh = (const __nv_bfloat16*)(sm);
    const __nv_bfloat16* sAl = (const __nv_bfloat16*)(sm + TBYTES);
    const __nv_bfloat16* sBh = (const __nv_bfloat16*)(sm + 2 * TBYTES);
    const __nv_bfloat16* sBl = (const __nv_bfloat16*)(sm + 3 * TBYTES);
    uint32_t* sAhw = (uint32_t*)(sm);
    uint32_t* sAlw = (uint32_t*)(sm + TBYTES);
    uint32_t* sBhw = (uint32_t*)(sm + 2 * TBYTES);
    uint32_t* sBlw = (uint32_t*)(sm + 3 * TBYTES);
    const int abase = (warp * 16 + g) * TSTRIDE + lt2;

    // 32 scalar accumulators
    float c00=0,c01=0,c02=0,c03=0, c10=0,c11=0,c12=0,c13=0;
    float c20=0,c21=0,c22=0,c23=0, c30=0,c31=0,c32=0,c33=0;
    float c40=0,c41=0,c42=0,c43=0, c50=0,c51=0,c52=0,c53=0;
    float c60=0,c61=0,c62=0,c63=0, c70=0,c71=0,c72=0,c73=0;
    // 32 scalar A fragments
    uint32_t ah00,ah01,ah02,ah03, ah10,ah11,ah12,ah13;
    uint32_t ah20,ah21,ah22,ah23, ah30,ah31,ah32,ah33;
    uint32_t al00,al01,al02,al03, al10,al11,al12,al13;
    uint32_t al20,al21,al22,al23, al30,al31,al32,al33;

    const int bn_l = lane & 7;        // n low bits
    const int bp_l = lane >> 3;       // pair low bits

    // prefetch registers
    float4 va[8];
    float2 vb[16];

    // LDG chunk k0 into registers
    auto ldg_chunk = [&](int k0) {
        #pragma unroll
        for (int it = 0; it < 8; it++) {
            int idx = tid + it * 128;
            int m  = idx >> 4;
            int c4 = idx & 15;
            va[it] = *(const float4*)(X + (size_t)(m0 + m) * D_MODEL
                                        + k0 + 4 * c4);
        }
        #pragma unroll
        for (int it = 0; it < 16; it++) {
            int n = bn_l + 8 * (it & 7);
            int p = bp_l + 4 * warp + 16 * (it >> 3);
            const float* w0 = W + (size_t)(k0 + 2 * p) * N + n0 + n;
            vb[it].x = w0[0];
            vb[it].y = w0[N];
        }
    };

    // convert + store registers to smem
    auto sts_chunk = [&]() {
        #pragma unroll
        for (int it = 0; it < 8; it++) {
            int idx = tid + it * 128;
            int m  = idx >> 4;
            int c4 = idx & 15;
            float4 v = va[it];
            uint2 h, l;
            h.x = pack_bf16(v.x, v.y);
            h.y = pack_bf16(v.z, v.w);
            l.x = pack_bf16(v.x - bf16_rnf(v.x), v.y - bf16_rnf(v.y));
            l.y = pack_bf16(v.z - bf16_rnf(v.z), v.w - bf16_rnf(v.w));
            int woff = m * 36 + 2 * c4;
            *(uint2*)(sAhw + woff) = h;
            *(uint2*)(sAlw + woff) = l;
        }
        #pragma unroll
        for (int it = 0; it < 16; it++) {
            int n = bn_l + 8 * (it & 7);
            int p = bp_l + 4 * warp + 16 * (it >> 3);
            float v0 = vb[it].x;
            float v1 = vb[it].y;
            int woff = n * 36 + p;
            sBhw[woff] = pack_bf16(v0, v1);
            sBlw[woff] = pack_bf16(v0 - bf16_rnf(v0), v1 - bf16_rnf(v1));
        }
    };

    ldg_chunk(0);

    for (int t = 0; t < D_MODEL / 64; t++) {
        __syncthreads();       // all warps done reading smem from prev chunk
        sts_chunk();
        __syncthreads();
        if (t + 1 < D_MODEL / 64) ldg_chunk((t + 1) * 64);  // in flight over mma

        LOAD_A(0); LOAD_A(1); LOAD_A(2); LOAD_A(3);
        MMA_NF(0); MMA_NF(1); MMA_NF(2); MMA_NF(3);
        MMA_NF(4); MMA_NF(5); MMA_NF(6); MMA_NF(7);
    }

    const int m_g  = m0 + warp * 16 + g;
    const int m_g8 = m_g + 8;
    STORE_NF(0); STORE_NF(1); STORE_NF(2); STORE_NF(3);
    STORE_NF(4); STORE_NF(5); STORE_NF(6); STORE_NF(7);
}

// ---------------------------------------------------------------------------
// Elementwise scatter (measured 72us): g_QKV -> Q/K/V bf16 hi/lo.
// ---------------------------------------------------------------------------
__global__ __launch_bounds__(256) void qkv_scatter()
{
    int j = blockIdx.x * 256 + threadIdx.x;
    int m = j >> 10;
    int t = j & 1023;
    int h = t >> 6;
    int dd = t & 63;
    const float QSCALE = 0.18033688011112042f;    // 0.125 * log2(e)

    const float* p = g_QKV + (size_t)m * N_QKV + t * 3;
    float q = p[0] * QSCALE;
    float k = p[1];
    float v = p[2];

    int b = m >> 11;
    int s = m & 2047;
    size_t iqk = (((size_t)(b * NH + h)) * SEQ + s) * DH + dd;
    size_t iv  = (((size_t)(b * NH + h)) * DH + dd) * SEQ + s;

    __nv_bfloat16 qh = __float2bfloat16(q);
    g_Qhi[iqk] = qh;
    g_Qlo[iqk] = __float2bfloat16(q - __bfloat162float(qh));
    __nv_bfloat16 kh = __float2bfloat16(k);
    g_Khi[iqk] = kh;
    g_Klo[iqk] = __float2bfloat16(k - __bfloat162float(kh));
    __nv_bfloat16 vh = __float2bfloat16(v);
    g_Vthi[iv] = vh;
    g_Vtlo[iv] = __float2bfloat16(v - __bfloat162float(vh));
}

// ---------------------------------------------------------------------------
// Flash attention via mma.sync m16n8k16 bf16 (R5 VERBATIM — proven).
// ---------------------------------------------------------------------------
__global__ __launch_bounds__(128) void flash_attn_mma()
{
    extern __shared__ char sm[];
    const uint32_t smb = smem_u32(sm);

    const int tid  = threadIdx.x;
    const int warp = tid >> 5;
    const int lane = tid & 31;
    const int g    = lane >> 2;
    const int lt   = lane & 3;
    const int bh   = blockIdx.x;
    const int q0   = blockIdx.y * 64;

    uint32_t aQh[16], aQl[16];
    {
        const size_t qb = (size_t)bh * SEQ + q0 + warp * 16;
        const __nv_bfloat16* Qh0 = g_Qhi + (qb + g) * DH;
        const __nv_bfloat16* Qh8 = g_Qhi + (qb + g + 8) * DH;
        const __nv_bfloat16* Ql0 = g_Qlo + (qb + g) * DH;
        const __nv_bfloat16* Ql8 = g_Qlo + (qb + g + 8) * DH;
        #pragma unroll
        for (int kg = 0; kg < 4; kg++) {
            int d0 = kg * 16 + 2 * lt;
            aQh[4*kg+0] = *(const uint32_t*)(Qh0 + d0);
            aQh[4*kg+1] = *(const uint32_t*)(Qh8 + d0);
            aQh[4*kg+2] = *(const uint32_t*)(Qh0 + d0 + 8);
            aQh[4*kg+3] = *(const uint32_t*)(Qh8 + d0 + 8);
            aQl[4*kg+0] = *(const uint32_t*)(Ql0 + d0);
            aQl[4*kg+1] = *(const uint32_t*)(Ql8 + d0);
            aQl[4*kg+2] = *(const uint32_t*)(Ql0 + d0 + 8);
            aQl[4*kg+3] = *(const uint32_t*)(Ql8 + d0 + 8);
        }
    }

    float O[8][4];
    #pragma unroll
    for (int i = 0; i < 8; i++)
        #pragma unroll
        for (int j = 0; j < 4; j++) O[i][j] = 0.0f;
    float m0 = -1e30f, m1 = -1e30f, l0 = 0.0f, l1 = 0.0f;

    const __nv_bfloat16* baseKh = g_Khi + (size_t)bh * SEQ * DH;
    const __nv_bfloat16* baseKl = g_Klo + (size_t)bh * SEQ * DH;
    const __nv_bfloat16* baseVh = g_Vthi + (size_t)bh * DH * SEQ;
    const __nv_bfloat16* baseVl = g_Vtlo + (size_t)bh * DH * SEQ;

    auto load_stage = [&](int buf, int kt) {
        #pragma unroll
        for (int it = 0; it < 16; it++) {
            int i = tid + it * 128;
            int tensor = i >> 9;
            int rem = i & 511;
            int row = rem >> 3;
            int c8  = rem & 7;
            const __nv_bfloat16* src;
            if (tensor == 0)      src = baseKh + (size_t)(kt + row) * DH + c8 * 8;
            else if (tensor == 1) src = baseKl + (size_t)(kt + row) * DH + c8 * 8;
            else if (tensor == 2) src = baseVh + (size_t)row * SEQ + kt + c8 * 8;
            else                  src = baseVl + (size_t)row * SEQ + kt + c8 * 8;
            uint32_t dst = smb + buf * STAGEB + tensor * TBYTES
                         + row * (TSTRIDE * 2) + c8 * 16;
            CP_ASYNC16(dst, src);
        }
        CP_COMMIT();
    };

    load_stage(0, 0);

    const int NT = SEQ / 64;
    for (int t = 0; t < NT; t++) {
        if (t + 1 < NT) { load_stage((t + 1) & 1, (t + 1) * 64); }
        if (t + 1 < NT) { CP_WAIT1(); } else { CP_WAIT0(); }
        __syncthreads();

        const int bb = t & 1;
        const __nv_bfloat16* sKhi = (const __nv_bfloat16*)(sm + bb*STAGEB);
        const __nv_bfloat16* sKlo = (const __nv_bfloat16*)(sm + bb*STAGEB + TBYTES);
        const __nv_bfloat16* sVhi = (const __nv_bfloat16*)(sm + bb*STAGEB + 2*TBYTES);
        const __nv_bfloat16* sVlo = (const __nv_bfloat16*)(sm + bb*STAGEB + 3*TBYTES);

        float s[8][4];
        #pragma unroll
        for (int i = 0; i < 8; i++)
            #pragma unroll
            for (int j = 0; j < 4; j++) s[i][j] = 0.0f;

        #pragma unroll
        for (int nf = 0; nf < 8; nf++) {
            #pragma unroll
            for (int kg = 0; kg < 4; kg++) {
                int off = (nf * 8 + g) * TSTRIDE + kg * 16 + 2 * lt;
                uint32_t b0h = *(const uint32_t*)(sKhi + off);
                uint32_t b1h = *(const uint32_t*)(sKhi + off + 8);
                uint32_t b0l = *(const uint32_t*)(sKlo + off);
                uint32_t b1l = *(const uint32_t*)(sKlo + off + 8);
                mma_bf16(s[nf], &aQh[4*kg], b0h, b1h);
                mma_bf16(s[nf], &aQh[4*kg], b0l, b1l);
                mma_bf16(s[nf], &aQl[4*kg], b0h, b1h);
            }
        }

        float r0 = -1e30f, r1 = -1e30f;
        #pragma unroll
        for (int nf = 0; nf < 8; nf++) {
            r0 = fmaxf(r0, fmaxf(s[nf][0], s[nf][1]));
            r1 = fmaxf(r1, fmaxf(s[nf][2], s[nf][3]));
        }
        r0 = fmaxf(r0, __shfl_xor_sync(0xffffffffu, r0, 1));
        r0 = fmaxf(r0, __shfl_xor_sync(0xffffffffu, r0, 2));
        r1 = fmaxf(r1, __shfl_xor_sync(0xffffffffu, r1, 1));
        r1 = fmaxf(r1, __shfl_xor_sync(0xffffffffu, r1, 2));

        float mn0 = fmaxf(m0, r0), mn1 = fmaxf(m1, r1);
        float cr0 = exp2_fast(m0 - mn0), cr1 = exp2_fast(m1 - mn1);
        m0 = mn0; m1 = mn1;
        l0 *= cr0; l1 *= cr1;
        #pragma unroll
        for (int i = 0; i < 8; i++) {
            O[i][0] *= cr0; O[i][1] *= cr0;
            O[i][2] *= cr1; O[i][3] *= cr1;
        }

        uint32_t phi[16], plo[16];
        #pragma unroll
        for (int nf = 0; nf < 8; nf++) {
            float p0 = exp2_fast(s[nf][0] - m0);
            float p1 = exp2_fast(s[nf][1] - m0);
            float p2 = exp2_fast(s[nf][2] - m1);
            float p3 = exp2_fast(s[nf][3] - m1);
            l0 += p0 + p1;
            l1 += p2 + p3;
            phi[2*nf+0] = pack_bf16(p0, p1);
            phi[2*nf+1] = pack_bf16(p2, p3);
            plo[2*nf+0] = pack_bf16(p0 - bf16_rnf(p0), p1 - bf16_rnf(p1));
            plo[2*nf+1] = pack_bf16(p2 - bf16_rnf(p2), p3 - bf16_rnf(p3));
        }

        #pragma unroll
        for (int nfd = 0; nfd < 8; nfd++) {
            #pragma unroll
            for (int kg = 0; kg < 4; kg++) {
                int off = (nfd * 8 + g) * TSTRIDE + kg * 16 + 2 * lt;
                uint32_t b0h = *(const uint32_t*)(sVhi + off);
                uint32_t b1h = *(const uint32_t*)(sVhi + off + 8);
                uint32_t b0l = *(const uint32_t*)(sVlo + off);
                uint32_t b1l = *(const uint32_t*)(sVlo + off + 8);
                mma_bf16(O[nfd], &phi[4*kg], b0h, b1h);
                mma_bf16(O[nfd], &phi[4*kg], b0l, b1l);
                mma_bf16(O[nfd], &plo[4*kg], b0h, b1h);
            }
        }
        __syncthreads();
    }

    l0 += __shfl_xor_sync(0xffffffffu, l0, 1);
    l0 += __shfl_xor_sync(0xffffffffu, l0, 2);
    l1 += __shfl_xor_sync(0xffffffffu, l1, 1);
    l1 += __shfl_xor_sync(0xffffffffu, l1, 2);

    float i0 = 1.0f / l0, i1 = 1.0f / l1;
    int b  = bh >> 4;
    int hh = bh & 15;
    int qr0 = q0 + warp * 16 + g;
    int qr1 = qr0 + 8;
    float* A0 = g_A + (((size_t)b * SEQ + qr0) * NH + hh) * DH;
    float* A1 = g_A + (((size_t)b * SEQ + qr1) * NH + hh) * DH;
    #pragma unroll
    for (int nfd = 0; nfd < 8; nfd++) {
        int d = nfd * 8 + 2 * lt;
        float2 u, w;
        u.x = O[nfd][0] * i0; u.y = O[nfd][1] * i0;
        w.x = O[nfd][2] * i1; w.y = O[nfd][3] * i1;
        *(float2*)(A0 + d) = u;
        *(float2*)(A1 + d) = w;
    }
}

extern "C" void kernel_launch(void* const* d_in, const int* in_sizes, int n_in,
                              void* d_out, int out_size)
{
    const float* X     = (const float*)d_in[0];
    const float* W_qkv = (const float*)d_in[1];
    const float* W_out = (const float*)d_in[2];
    float* out = (float*)d_out;

    float* gQKV;
    float* gA;
    cudaGetSymbolAddress((void**)&gQKV, g_QKV);
    cudaGetSymbolAddress((void**)&gA, g_A);

    cudaFuncSetAttribute(flash_attn_mma,
                         cudaFuncAttributeMaxDynamicSharedMemorySize, SMEM_ATTN);
    cudaFuncSetAttribute(gemm_fused<N_QKV>,
                         cudaFuncAttributeMaxDynamicSharedMemorySize, SMEM_GEMM);
    cudaFuncSetAttribute(gemm_fused<D_MODEL>,
                         cudaFuncAttributeMaxDynamicSharedMemorySize, SMEM_GEMM);

    gemm_fused<N_QKV><<<dim3(N_QKV / 64, M_ROWS / 64), 128, SMEM_GEMM>>>(
        X, W_qkv, gQKV);

    qkv_scatter<<<(M_ROWS * 1024) / 256, 256>>>();

    flash_attn_mma<<<dim3(BH, SEQ / 64), 128, SMEM_ATTN>>>();

    gemm_fused<D_MODEL><<<dim3(D_MODEL / 64, M_ROWS / 64), 128, SMEM_GEMM>>>(
        gA, W_out, out);
}

// round 17
// speedup vs baseline: 1.1498x; 1.1498x over previous
#include <cuda_runtime.h>
#include <cuda_bf16.h>
#include <cstdint>

#define D_MODEL 1024
#define NH 16
#define DH 64
#define SEQ 2048
#define BATCH 2
#define BH (BATCH * NH)        // 32
#define M_ROWS (BATCH * SEQ)   // 4096
#define N_QKV (3 * NH * DH)    // 3072

// Scratch
__device__ __align__(16) float g_QKV[(size_t)M_ROWS * N_QKV];
__device__ __align__(16) __nv_bfloat16 g_Qhi[(size_t)BH * SEQ * DH];
__device__ __align__(16) __nv_bfloat16 g_Qlo[(size_t)BH * SEQ * DH];
__device__ __align__(16) __nv_bfloat16 g_Khi[(size_t)BH * SEQ * DH];
__device__ __align__(16) __nv_bfloat16 g_Klo[(size_t)BH * SEQ * DH];
__device__ __align__(16) __nv_bfloat16 g_Vthi[(size_t)BH * DH * SEQ];
__device__ __align__(16) __nv_bfloat16 g_Vtlo[(size_t)BH * DH * SEQ];
__device__ float g_A[(size_t)M_ROWS * D_MODEL];

// ---------------------------------------------------------------------------
__device__ __forceinline__ float exp2_fast(float x)
{
    x = fmaxf(x, -80.0f);
    float z = x + 12582912.0f;
    int   n = __float_as_int(z) - 0x4B400000;
    float f = x - (z - 12582912.0f);
    float p = 1.3369700e-3f;
    p = fmaf(p, f, 9.6179365e-3f);
    p = fmaf(p, f, 5.5503264e-2f);
    p = fmaf(p, f, 2.4022736e-1f);
    p = fmaf(p, f, 6.9314693e-1f);
    p = fmaf(p, f, 1.0f);
    return __int_as_float(__float_as_int(p) + (n << 23));
}

__device__ __forceinline__ uint32_t smem_u32(const void* p) {
    uint32_t a;
    asm("{ .reg .u64 t; cvta.to.shared.u64 t, %1; cvt.u32.u64 %0, t; }"
        : "=r"(a) : "l"(p));
    return a;
}

// returns {second arg in bits 31:16, first arg in bits 15:0}
__device__ __forceinline__ uint32_t pack_bf16(float lo_elem, float hi_elem) {
    uint32_t r;
    asm("cvt.rn.bf16x2.f32 %0, %1, %2;" : "=r"(r) : "f"(hi_elem), "f"(lo_elem));
    return r;
}

__device__ __forceinline__ float bf16_rnf(float x) {
    return __bfloat162float(__float2bfloat16(x));
}

__device__ __forceinline__ void mma_bf16(float* c, const uint32_t* a,
                                         uint32_t b0, uint32_t b1) {
    asm volatile(
        "mma.sync.aligned.m16n8k16.row.col.f32.bf16.bf16.f32 "
        "{%0,%1,%2,%3}, {%4,%5,%6,%7}, {%8,%9}, {%0,%1,%2,%3};"
        : "+f"(c[0]), "+f"(c[1]), "+f"(c[2]), "+f"(c[3])
        : "r"(a[0]), "r"(a[1]), "r"(a[2]), "r"(a[3]), "r"(b0), "r"(b1));
}

#define MMA4(C0,C1,C2,C3,A0,A1,A2,A3,B0,B1) \
    asm volatile("mma.sync.aligned.m16n8k16.row.col.f32.bf16.bf16.f32 " \
        "{%0,%1,%2,%3}, {%4,%5,%6,%7}, {%8,%9}, {%0,%1,%2,%3};" \
        : "+f"(C0), "+f"(C1), "+f"(C2), "+f"(C3) \
        : "r"(A0), "r"(A1), "r"(A2), "r"(A3), "r"(B0), "r"(B1))

#define CP_ASYNC16(dst, src) \
    asm volatile("cp.async.cg.shared.global [%0], [%1], 16;" \
                 :: "r"(dst), "l"(src))
#define CP_COMMIT() asm volatile("cp.async.commit_group;" ::: "memory")
#define CP_WAIT0()  asm volatile("cp.async.wait_group 0;" ::: "memory")
#define CP_WAIT1()  asm volatile("cp.async.wait_group 1;" ::: "memory")

// ---------------------------------------------------------------------------
// Geometry
// ---------------------------------------------------------------------------
#define TSTRIDE 72
#define TBYTES  (64 * TSTRIDE * 2)      // 9216  (64-row tensor)
#define ABYTES  (128 * TSTRIDE * 2)     // 18432 (128-row A tensor)
#define STAGEB  (4 * TBYTES)            // 36864
#define SMEM_ATTN (2 * STAGEB)          // flash double-buffered: 73728
#define SMEM_GBIG (2 * ABYTES + 2 * TBYTES)  // big gemm: 55296
#define SMEM_GSML STAGEB                     // small gemm: 36864

// Shared per-warp fragment/mma macros (operate on kernel-local names)
#define LOAD_A(KG) do {                                         \
    int r0_ = abase + (KG) * 16;                                \
    int r8_ = r0_ + 8 * TSTRIDE;                                \
    ah##KG##0 = *(const uint32_t*)(sAh + r0_);                  \
    ah##KG##1 = *(const uint32_t*)(sAh + r8_);                  \
    ah##KG##2 = *(const uint32_t*)(sAh + r0_ + 8);              \
    ah##KG##3 = *(const uint32_t*)(sAh + r8_ + 8);              \
    al##KG##0 = *(const uint32_t*)(sAl + r0_);                  \
    al##KG##1 = *(const uint32_t*)(sAl + r8_);                  \
    al##KG##2 = *(const uint32_t*)(sAl + r0_ + 8);              \
    al##KG##3 = *(const uint32_t*)(sAl + r8_ + 8);              \
} while (0)

#define MMA_KG(NF, KG, BOFF) do {                               \
    uint32_t b0h_ = *(const uint32_t*)(sBh + (BOFF) + (KG)*16);     \
    uint32_t b1h_ = *(const uint32_t*)(sBh + (BOFF) + (KG)*16 + 8); \
    uint32_t b0l_ = *(const uint32_t*)(sBl + (BOFF) + (KG)*16);     \
    uint32_t b1l_ = *(const uint32_t*)(sBl + (BOFF) + (KG)*16 + 8); \
    MMA4(c##NF##0, c##NF##1, c##NF##2, c##NF##3,                \
         ah##KG##0, ah##KG##1, ah##KG##2, ah##KG##3, b0h_, b1h_); \
    MMA4(c##NF##0, c##NF##1, c##NF##2, c##NF##3,                \
         ah##KG##0, ah##KG##1, ah##KG##2, ah##KG##3, b0l_, b1l_); \
    MMA4(c##NF##0, c##NF##1, c##NF##2, c##NF##3,                \
         al##KG##0, al##KG##1, al##KG##2, al##KG##3, b0h_, b1h_); \
} while (0)

#define MMA_NF(NF) do {                                         \
    int boff_ = ((NF) * 8 + g) * TSTRIDE + lt2;                 \
    MMA_KG(NF, 0, boff_);                                       \
    MMA_KG(NF, 1, boff_);                                       \
    MMA_KG(NF, 2, boff_);                                       \
    MMA_KG(NF, 3, boff_);                                       \
} while (0)

#define STORE_NF(NF) do {                                       \
    int n_ = n0 + (NF) * 8 + lt2;                               \
    float2 u_; u_.x = c##NF##0; u_.y = c##NF##1;                \
    float2 w_; w_.x = c##NF##2; w_.y = c##NF##3;                \
    *(float2*)(C + (size_t)m_g  * N + n_) = u_;                 \
    *(float2*)(C + (size_t)m_g8 * N + n_) = w_;                 \
} while (0)

#define DECLARE_ACC_FRAG()                                      \
    float c00=0,c01=0,c02=0,c03=0, c10=0,c11=0,c12=0,c13=0;     \
    float c20=0,c21=0,c22=0,c23=0, c30=0,c31=0,c32=0,c33=0;     \
    float c40=0,c41=0,c42=0,c43=0, c50=0,c51=0,c52=0,c53=0;     \
    float c60=0,c61=0,c62=0,c63=0, c70=0,c71=0,c72=0,c73=0;     \
    uint32_t ah00,ah01,ah02,ah03, ah10,ah11,ah12,ah13;          \
    uint32_t ah20,ah21,ah22,ah23, ah30,ah31,ah32,ah33;          \
    uint32_t al00,al01,al02,al03, al10,al11,al12,al13;          \
    uint32_t al20,al21,al22,al23, al30,al31,al32,al33

// ---------------------------------------------------------------------------
// BIG fused-split mma GEMM (R15 verbatim): tile 128m x 64n, 256 threads.
// grid: (N/64, M_ROWS/128), block 256.
// ---------------------------------------------------------------------------
template <int N>
__global__ __launch_bounds__(256) void gemm_big(
    const float* __restrict__ X, const float* __restrict__ W,
    float* __restrict__ C)
{
    extern __shared__ char sm[];

    const int tid  = threadIdx.x;
    const int warp = tid >> 5;          // 0..7
    const int lane = tid & 31;
    const int g    = lane >> 2;
    const int lt2  = (lane & 3) * 2;
    const int n0   = blockIdx.x * 64;
    const int m0   = blockIdx.y * 128;

    const __nv_bfloat16* sAh = (const __nv_bfloat16*)(sm);
    const __nv_bfloat16* sAl = (const __nv_bfloat16*)(sm + ABYTES);
    const __nv_bfloat16* sBh = (const __nv_bfloat16*)(sm + 2 * ABYTES);
    const __nv_bfloat16* sBl = (const __nv_bfloat16*)(sm + 2 * ABYTES + TBYTES);
    uint32_t* sAhw = (uint32_t*)(sm);
    uint32_t* sAlw = (uint32_t*)(sm + ABYTES);
    uint32_t* sBhw = (uint32_t*)(sm + 2 * ABYTES);
    uint32_t* sBlw = (uint32_t*)(sm + 2 * ABYTES + TBYTES);
    const int abase = (warp * 16 + g) * TSTRIDE + lt2;

    DECLARE_ACC_FRAG();

    const int bn_l = lane & 7;
    const int bp_l = lane >> 3;

    for (int t = 0; t < D_MODEL / 64; t++) {
        const int k0 = t * 64;
        __syncthreads();

        #pragma unroll
        for (int it = 0; it < 8; it++) {
            int idx = tid + it * 256;
            int m  = idx >> 4;
            int c4 = idx & 15;
            float4 v = *(const float4*)(X + (size_t)(m0 + m) * D_MODEL
                                          + k0 + 4 * c4);
            uint2 h, l;
            h.x = pack_bf16(v.x, v.y);
            h.y = pack_bf16(v.z, v.w);
            l.x = pack_bf16(v.x - bf16_rnf(v.x), v.y - bf16_rnf(v.y));
            l.y = pack_bf16(v.z - bf16_rnf(v.z), v.w - bf16_rnf(v.w));
            int woff = m * 36 + 2 * c4;
            *(uint2*)(sAhw + woff) = h;
            *(uint2*)(sAlw + woff) = l;
        }
        #pragma unroll
        for (int it = 0; it < 8; it++) {
            int n = bn_l + 8 * it;
            int p = bp_l + 4 * warp;
            const float* w0 = W + (size_t)(k0 + 2 * p) * N + n0 + n;
            float v0 = w0[0];
            float v1 = w0[N];
            int woff = n * 36 + p;
            sBhw[woff] = pack_bf16(v0, v1);
            sBlw[woff] = pack_bf16(v0 - bf16_rnf(v0), v1 - bf16_rnf(v1));
        }
        __syncthreads();

        LOAD_A(0); LOAD_A(1); LOAD_A(2); LOAD_A(3);
        MMA_NF(0); MMA_NF(1); MMA_NF(2); MMA_NF(3);
        MMA_NF(4); MMA_NF(5); MMA_NF(6); MMA_NF(7);
    }

    const int m_g  = m0 + warp * 16 + g;
    const int m_g8 = m_g + 8;
    STORE_NF(0); STORE_NF(1); STORE_NF(2); STORE_NF(3);
    STORE_NF(4); STORE_NF(5); STORE_NF(6); STORE_NF(7);
}

// ---------------------------------------------------------------------------
// SMALL fused-split mma GEMM (R14 verbatim): tile 64m x 64n, 128 threads.
// grid: (N/64, M_ROWS/64), block 128.
// ---------------------------------------------------------------------------
template <int N>
__global__ __launch_bounds__(128) void gemm_small(
    const float* __restrict__ X, const float* __restrict__ W,
    float* __restrict__ C)
{
    extern __shared__ char sm[];

    const int tid  = threadIdx.x;
    const int warp = tid >> 5;          // 0..3
    const int lane = tid & 31;
    const int g    = lane >> 2;
    const int lt2  = (lane & 3) * 2;
    const int n0   = blockIdx.x * 64;
    const int m0   = blockIdx.y * 64;

    const __nv_bfloat16* sAh = (const __nv_bfloat16*)(sm);
    const __nv_bfloat16* sAl = (const __nv_bfloat16*)(sm + TBYTES);
    const __nv_bfloat16* sBh = (const __nv_bfloat16*)(sm + 2 * TBYTES);
    const __nv_bfloat16* sBl = (const __nv_bfloat16*)(sm + 3 * TBYTES);
    uint32_t* sAhw = (uint32_t*)(sm);
    uint32_t* sAlw = (uint32_t*)(sm + TBYTES);
    uint32_t* sBhw = (uint32_t*)(sm + 2 * TBYTES);
    uint32_t* sBlw = (uint32_t*)(sm + 3 * TBYTES);
    const int abase = (warp * 16 + g) * TSTRIDE + lt2;

    DECLARE_ACC_FRAG();

    const int bn_l = lane & 7;
    const int bp_l = lane >> 3;

    for (int t = 0; t < D_MODEL / 64; t++) {
        const int k0 = t * 64;
        __syncthreads();

        #pragma unroll
        for (int it = 0; it < 8; it++) {
            int idx = tid + it * 128;
            int m  = idx >> 4;
            int c4 = idx & 15;
            float4 v = *(const float4*)(X + (size_t)(m0 + m) * D_MODEL
                                          + k0 + 4 * c4);
            uint2 h, l;
            h.x = pack_bf16(v.x, v.y);
            h.y = pack_bf16(v.z, v.w);
            l.x = pack_bf16(v.x - bf16_rnf(v.x), v.y - bf16_rnf(v.y));
            l.y = pack_bf16(v.z - bf16_rnf(v.z), v.w - bf16_rnf(v.w));
            int woff = m * 36 + 2 * c4;
            *(uint2*)(sAhw + woff) = h;
            *(uint2*)(sAlw + woff) = l;
        }
        #pragma unroll
        for (int it = 0; it < 16; it++) {
            int n = bn_l + 8 * (it & 7);
            int p = bp_l + 4 * warp + 16 * (it >> 3);
            const float* w0 = W + (size_t)(k0 + 2 * p) * N + n0 + n;
            float v0 = w0[0];
            float v1 = w0[N];
            int woff = n * 36 + p;
            sBhw[woff] = pack_bf16(v0, v1);
            sBlw[woff] = pack_bf16(v0 - bf16_rnf(v0), v1 - bf16_rnf(v1));
        }
        __syncthreads();

        LOAD_A(0); LOAD_A(1); LOAD_A(2); LOAD_A(3);
        MMA_NF(0); MMA_NF(1); MMA_NF(2); MMA_NF(3);
        MMA_NF(4); MMA_NF(5); MMA_NF(6); MMA_NF(7);
    }

    const int m_g  = m0 + warp * 16 + g;
    const int m_g8 = m_g + 8;
    STORE_NF(0); STORE_NF(1); STORE_NF(2); STORE_NF(3);
    STORE_NF(4); STORE_NF(5); STORE_NF(6); STORE_NF(7);
}

// ---------------------------------------------------------------------------
// Elementwise scatter (measured 72us): g_QKV -> Q/K/V bf16 hi/lo.
// ---------------------------------------------------------------------------
__global__ __launch_bounds__(256) void qkv_scatter()
{
    int j = blockIdx.x * 256 + threadIdx.x;
    int m = j >> 10;
    int t = j & 1023;
    int h = t >> 6;
    int dd = t & 63;
    const float QSCALE = 0.18033688011112042f;    // 0.125 * log2(e)

    const float* p = g_QKV + (size_t)m * N_QKV + t * 3;
    float q = p[0] * QSCALE;
    float k = p[1];
    float v = p[2];

    int b = m >> 11;
    int s = m & 2047;
    size_t iqk = (((size_t)(b * NH + h)) * SEQ + s) * DH + dd;
    size_t iv  = (((size_t)(b * NH + h)) * DH + dd) * SEQ + s;

    __nv_bfloat16 qh = __float2bfloat16(q);
    g_Qhi[iqk] = qh;
    g_Qlo[iqk] = __float2bfloat16(q - __bfloat162float(qh));
    __nv_bfloat16 kh = __float2bfloat16(k);
    g_Khi[iqk] = kh;
    g_Klo[iqk] = __float2bfloat16(k - __bfloat162float(kh));
    __nv_bfloat16 vh = __float2bfloat16(v);
    g_Vthi[iv] = vh;
    g_Vtlo[iv] = __float2bfloat16(v - __bfloat162float(vh));
}

// ---------------------------------------------------------------------------
// Flash attention via mma.sync m16n8k16 bf16 (R5 VERBATIM — proven).
// ---------------------------------------------------------------------------
__global__ __launch_bounds__(128) void flash_attn_mma()
{
    extern __shared__ char sm[];
    const uint32_t smb = smem_u32(sm);

    const int tid  = threadIdx.x;
    const int warp = tid >> 5;
    const int lane = tid & 31;
    const int g    = lane >> 2;
    const int lt   = lane & 3;
    const int bh   = blockIdx.x;
    const int q0   = blockIdx.y * 64;

    uint32_t aQh[16], aQl[16];
    {
        const size_t qb = (size_t)bh * SEQ + q0 + warp * 16;
        const __nv_bfloat16* Qh0 = g_Qhi + (qb + g) * DH;
        const __nv_bfloat16* Qh8 = g_Qhi + (qb + g + 8) * DH;
        const __nv_bfloat16* Ql0 = g_Qlo + (qb + g) * DH;
        const __nv_bfloat16* Ql8 = g_Qlo + (qb + g + 8) * DH;
        #pragma unroll
        for (int kg = 0; kg < 4; kg++) {
            int d0 = kg * 16 + 2 * lt;
            aQh[4*kg+0] = *(const uint32_t*)(Qh0 + d0);
            aQh[4*kg+1] = *(const uint32_t*)(Qh8 + d0);
            aQh[4*kg+2] = *(const uint32_t*)(Qh0 + d0 + 8);
            aQh[4*kg+3] = *(const uint32_t*)(Qh8 + d0 + 8);
            aQl[4*kg+0] = *(const uint32_t*)(Ql0 + d0);
            aQl[4*kg+1] = *(const uint32_t*)(Ql8 + d0);
            aQl[4*kg+2] = *(const uint32_t*)(Ql0 + d0 + 8);
            aQl[4*kg+3] = *(const uint32_t*)(Ql8 + d0 + 8);
        }
    }

    float O[8][4];
    #pragma unroll
    for (int i = 0; i < 8; i++)
        #pragma unroll
        for (int j = 0; j < 4; j++) O[i][j] = 0.0f;
    float m0 = -1e30f, m1 = -1e30f, l0 = 0.0f, l1 = 0.0f;

    const __nv_bfloat16* baseKh = g_Khi + (size_t)bh * SEQ * DH;
    const __nv_bfloat16* baseKl = g_Klo + (size_t)bh * SEQ * DH;
    const __nv_bfloat16* baseVh = g_Vthi + (size_t)bh * DH * SEQ;
    const __nv_bfloat16* baseVl = g_Vtlo + (size_t)bh * DH * SEQ;

    auto load_stage = [&](int buf, int kt) {
        #pragma unroll
        for (int it = 0; it < 16; it++) {
            int i = tid + it * 128;
            int tensor = i >> 9;
            int rem = i & 511;
            int row = rem >> 3;
            int c8  = rem & 7;
            const __nv_bfloat16* src;
            if (tensor == 0)      src = baseKh + (size_t)(kt + row) * DH + c8 * 8;
            else if (tensor == 1) src = baseKl + (size_t)(kt + row) * DH + c8 * 8;
            else if (tensor == 2) src = baseVh + (size_t)row * SEQ + kt + c8 * 8;
            else                  src = baseVl + (size_t)row * SEQ + kt + c8 * 8;
            uint32_t dst = smb + buf * STAGEB + tensor * TBYTES
                         + row * (TSTRIDE * 2) + c8 * 16;
            CP_ASYNC16(dst, src);
        }
        CP_COMMIT();
    };

    load_stage(0, 0);

    const int NT = SEQ / 64;
    for (int t = 0; t < NT; t++) {
        if (t + 1 < NT) { load_stage((t + 1) & 1, (t + 1) * 64); }
        if (t + 1 < NT) { CP_WAIT1(); } else { CP_WAIT0(); }
        __syncthreads();

        const int bb = t & 1;
        const __nv_bfloat16* sKhi = (const __nv_bfloat16*)(sm + bb*STAGEB);
        const __nv_bfloat16* sKlo = (const __nv_bfloat16*)(sm + bb*STAGEB + TBYTES);
        const __nv_bfloat16* sVhi = (const __nv_bfloat16*)(sm + bb*STAGEB + 2*TBYTES);
        const __nv_bfloat16* sVlo = (const __nv_bfloat16*)(sm + bb*STAGEB + 3*TBYTES);

        float s[8][4];
        #pragma unroll
        for (int i = 0; i < 8; i++)
            #pragma unroll
            for (int j = 0; j < 4; j++) s[i][j] = 0.0f;

        #pragma unroll
        for (int nf = 0; nf < 8; nf++) {
            #pragma unroll
            for (int kg = 0; kg < 4; kg++) {
                int off = (nf * 8 + g) * TSTRIDE + kg * 16 + 2 * lt;
                uint32_t b0h = *(const uint32_t*)(sKhi + off);
                uint32_t b1h = *(const uint32_t*)(sKhi + off + 8);
                uint32_t b0l = *(const uint32_t*)(sKlo + off);
                uint32_t b1l = *(const uint32_t*)(sKlo + off + 8);
                mma_bf16(s[nf], &aQh[4*kg], b0h, b1h);
                mma_bf16(s[nf], &aQh[4*kg], b0l, b1l);
                mma_bf16(s[nf], &aQl[4*kg], b0h, b1h);
            }
        }

        float r0 = -1e30f, r1 = -1e30f;
        #pragma unroll
        for (int nf = 0; nf < 8; nf++) {
            r0 = fmaxf(r0, fmaxf(s[nf][0], s[nf][1]));
            r1 = fmaxf(r1, fmaxf(s[nf][2], s[nf][3]));
        }
        r0 = fmaxf(r0, __shfl_xor_sync(0xffffffffu, r0, 1));
        r0 = fmaxf(r0, __shfl_xor_sync(0xffffffffu, r0, 2));
        r1 = fmaxf(r1, __shfl_xor_sync(0xffffffffu, r1, 1));
        r1 = fmaxf(r1, __shfl_xor_sync(0xffffffffu, r1, 2));

        float mn0 = fmaxf(m0, r0), mn1 = fmaxf(m1, r1);
        float cr0 = exp2_fast(m0 - mn0), cr1 = exp2_fast(m1 - mn1);
        m0 = mn0; m1 = mn1;
        l0 *= cr0; l1 *= cr1;
        #pragma unroll
        for (int i = 0; i < 8; i++) {
            O[i][0] *= cr0; O[i][1] *= cr0;
            O[i][2] *= cr1; O[i][3] *= cr1;
        }

        uint32_t phi[16], plo[16];
        #pragma unroll
        for (int nf = 0; nf < 8; nf++) {
            float p0 = exp2_fast(s[nf][0] - m0);
            float p1 = exp2_fast(s[nf][1] - m0);
            float p2 = exp2_fast(s[nf][2] - m1);
            float p3 = exp2_fast(s[nf][3] - m1);
            l0 += p0 + p1;
            l1 += p2 + p3;
            phi[2*nf+0] = pack_bf16(p0, p1);
            phi[2*nf+1] = pack_bf16(p2, p3);
            plo[2*nf+0] = pack_bf16(p0 - bf16_rnf(p0), p1 - bf16_rnf(p1));
            plo[2*nf+1] = pack_bf16(p2 - bf16_rnf(p2), p3 - bf16_rnf(p3));
        }

        #pragma unroll
        for (int nfd = 0; nfd < 8; nfd++) {
            #pragma unroll
            for (int kg = 0; kg < 4; kg++) {
                int off = (nfd * 8 + g) * TSTRIDE + kg * 16 + 2 * lt;
                uint32_t b0h = *(const uint32_t*)(sVhi + off);
                uint32_t b1h = *(const uint32_t*)(sVhi + off + 8);
                uint32_t b0l = *(const uint32_t*)(sVlo + off);
                uint32_t b1l = *(const uint32_t*)(sVlo + off + 8);
                mma_bf16(O[nfd], &phi[4*kg], b0h, b1h);
                mma_bf16(O[nfd], &phi[4*kg], b0l, b1l);
                mma_bf16(O[nfd], &plo[4*kg], b0h, b1h);
            }
        }
        __syncthreads();
    }

    l0 += __shfl_xor_sync(0xffffffffu, l0, 1);
    l0 += __shfl_xor_sync(0xffffffffu, l0, 2);
    l1 += __shfl_xor_sync(0xffffffffu, l1, 1);
    l1 += __shfl_xor_sync(0xffffffffu, l1, 2);

    float i0 = 1.0f / l0, i1 = 1.0f / l1;
    int b  = bh >> 4;
    int hh = bh & 15;
    int qr0 = q0 + warp * 16 + g;
    int qr1 = qr0 + 8;
    float* A0 = g_A + (((size_t)b * SEQ + qr0) * NH + hh) * DH;
    float* A1 = g_A + (((size_t)b * SEQ + qr1) * NH + hh) * DH;
    #pragma unroll
    for (int nfd = 0; nfd < 8; nfd++) {
        int d = nfd * 8 + 2 * lt;
        float2 u, w;
        u.x = O[nfd][0] * i0; u.y = O[nfd][1] * i0;
        w.x = O[nfd][2] * i1; w.y = O[nfd][3] * i1;
        *(float2*)(A0 + d) = u;
        *(float2*)(A1 + d) = w;
    }
}

extern "C" void kernel_launch(void* const* d_in, const int* in_sizes, int n_in,
                              void* d_out, int out_size)
{
    const float* X     = (const float*)d_in[0];
    const float* W_qkv = (const float*)d_in[1];
    const float* W_out = (const float*)d_in[2];
    float* out = (float*)d_out;

    float* gQKV;
    float* gA;
    cudaGetSymbolAddress((void**)&gQKV, g_QKV);
    cudaGetSymbolAddress((void**)&gA, g_A);

    cudaFuncSetAttribute(flash_attn_mma,
                         cudaFuncAttributeMaxDynamicSharedMemorySize, SMEM_ATTN);
    cudaFuncSetAttribute(gemm_big<N_QKV>,
                         cudaFuncAttributeMaxDynamicSharedMemorySize, SMEM_GBIG);
    cudaFuncSetAttribute(gemm_small<D_MODEL>,
                         cudaFuncAttributeMaxDynamicSharedMemorySize, SMEM_GSML);

    gemm_big<N_QKV><<<dim3(N_QKV / 64, M_ROWS / 128), 256, SMEM_GBIG>>>(
        X, W_qkv, gQKV);

    qkv_scatter<<<(M_ROWS * 1024) / 256, 256>>>();

    flash_attn_mma<<<dim3(BH, SEQ / 64), 128, SMEM_ATTN>>>();

    gemm_small<D_MODEL><<<dim3(D_MODEL / 64, M_ROWS / 64), 128, SMEM_GSML>>>(
        gA, W_out, out);
}